// round 12
// baseline (speedup 1.0000x reference)
#include <cuda_runtime.h>
#include <cuda_bf16.h>
#include <cstdint>
#include <cfloat>

// ---------------------------------------------------------------------------
// Problem constants
// ---------------------------------------------------------------------------
#define M_TOTAL 16384
#define K_CODES 8192
#define DIM     512
#define MT      64              // rows per CTA (2 CTAs/SM)
#define BN      256             // codes per chunk; warp tile 64x32
#define NCHUNK  (K_CODES / BN)  // 32
#define BK      64              // int8 K per pipeline step (64 B/row)
#define KSTEPS  (DIM / BK)      // 8
#define NSTEPS  (NCHUNK * KSTEPS) // 256
#define NTHR    256
#define IDXMASK 0x1FFFu         // 13 bits: code index embedded in mantissa

// ---------------------------------------------------------------------------
// Scratch (static device arrays: allocation-free rule)
// ---------------------------------------------------------------------------
__device__ char  g_Ax8[(size_t)M_TOTAL * DIM];   // int8(x)    8 MB
__device__ char  g_Be8[(size_t)K_CODES * DIM];   // int8(emb)  4 MB
__device__ float g_e2[K_CODES];
__device__ int   g_top8[M_TOTAL][8];
__device__ int   g_amax_x = 0;                   // abs-max bits (positive float)
__device__ int   g_amax_e = 0;

// ---------------------------------------------------------------------------
// Baseline-PTX helpers (no "a"-suffix arch features)
// ---------------------------------------------------------------------------
__device__ __forceinline__ uint32_t smem_u32(const void* p) {
    uint32_t a;
    asm("{ .reg .u64 t; cvta.to.shared.u64 t, %1; cvt.u32.u64 %0, t; }"
        : "=r"(a) : "l"(p));
    return a;
}

__device__ __forceinline__ void cp_async16(uint32_t dst, const void* src) {
    uint64_t g;
    asm("cvta.to.global.u64 %0, %1;" : "=l"(g) : "l"(src));
    asm volatile("cp.async.cg.shared.global [%0], [%1], 16;"
                 :: "r"(dst), "l"(g) : "memory");
}

__device__ __forceinline__ void cp_async16g(uint32_t dst, uint64_t gsrc) {
    asm volatile("cp.async.cg.shared.global [%0], [%1], 16;"
                 :: "r"(dst), "l"(gsrc) : "memory");
}
#define CP_COMMIT() asm volatile("cp.async.commit_group;" ::: "memory")

__device__ __forceinline__ void ldmatrix_x4(uint32_t& r0, uint32_t& r1,
                                            uint32_t& r2, uint32_t& r3,
                                            uint32_t addr) {
    asm volatile("ldmatrix.sync.aligned.m8n8.x4.shared.b16 {%0,%1,%2,%3}, [%4];"
                 : "=r"(r0), "=r"(r1), "=r"(r2), "=r"(r3) : "r"(addr));
}

// s8 IMMA m16n8k32 (sm_80 baseline PTX). Byte-level fragment layout equals
// the ldmatrix.b16 x4 tile layout used below.
__device__ __forceinline__ void mma_s8(int& d0, int& d1, int& d2, int& d3,
                                       uint32_t a0, uint32_t a1, uint32_t a2, uint32_t a3,
                                       uint32_t b0, uint32_t b1) {
    asm volatile(
        "mma.sync.aligned.m16n8k32.row.col.s32.s8.s8.s32 "
        "{%0,%1,%2,%3}, {%4,%5,%6,%7}, {%8,%9}, {%0,%1,%2,%3};"
        : "+r"(d0), "+r"(d1), "+r"(d2), "+r"(d3)
        : "r"(a0), "r"(a1), "r"(a2), "r"(a3), "r"(b0), "r"(b1));
}

// Embed code index in low 13 mantissa bits (single LOP3).
__device__ __forceinline__ float embed_idx(float s, uint32_t idx) {
    uint32_t r;
    asm("lop3.b32 %0, %1, %2, %3, 0xEA;"     // (a & b) | c
        : "=r"(r) : "r"(__float_as_uint(s)), "r"(~IDXMASK), "r"(idx));
    return __uint_as_float(r);
}

// Branchless top-2 (values carry their index).
__device__ __forceinline__ void top2f(float& b1, float& b2, float s) {
    float hi = fmaxf(b1, s);
    float lo = fminf(b1, s);
    b1 = hi;
    b2 = fmaxf(b2, lo);
}

// ---------------------------------------------------------------------------
// SMEM layout: A persistent 32 KB + B 4 stages x 16 KB = 96 KB, 2 CTAs/SM.
// Each B stage = 8 warp-private slices of 2 KB (32 rows x 64 B).
// ---------------------------------------------------------------------------
#define SM_A       0                          // 64 rows x 512 B
#define SM_B       32768
#define B_STAGE    16384
#define W_SLICE    2048
#define SMEM_TOTAL (SM_B + 4 * B_STAGE)       // 98304

// A smem addressing: row stride 512 B = 32 x 16B chunks; XOR-swizzle low 3
// chunk bits with (row & 7) -> conflict-free 8-row ldmatrix columns.
__device__ __forceinline__ uint32_t a_off(int row, int c) {
    return (uint32_t)(row * 512 + ((((c & 7) ^ (row & 7)) | (c & 24)) * 16));
}

// ---------------------------------------------------------------------------
// Kernel: e2[k] = ||emb_k||^2 (exact fp32)
// ---------------------------------------------------------------------------
__global__ void e2_kernel(const float* __restrict__ emb) {
    int row  = blockIdx.x * 8 + (threadIdx.x >> 5);
    int lane = threadIdx.x & 31;
    const float4* p = reinterpret_cast<const float4*>(emb + (size_t)row * DIM);
    float s = 0.f;
#pragma unroll
    for (int i = 0; i < 4; ++i) {
        float4 v = p[lane + i * 32];
        s += v.x * v.x + v.y * v.y + v.z * v.z + v.w * v.w;
    }
#pragma unroll
    for (int o = 16; o; o >>= 1) s += __shfl_xor_sync(0xffffffffu, s, o);
    if (lane == 0) g_e2[row] = s;
}

// ---------------------------------------------------------------------------
// Abs-max reduction kernels (positive float bits are monotone as ints).
// ---------------------------------------------------------------------------
__global__ void amax_kernel(const float* __restrict__ src, size_t n4, int* out) {
    __shared__ float red[8];
    size_t i = (size_t)blockIdx.x * blockDim.x + threadIdx.x;
    float m = 0.f;
    for (; i < n4; i += (size_t)gridDim.x * blockDim.x) {
        float4 v = reinterpret_cast<const float4*>(src)[i];
        m = fmaxf(m, fmaxf(fmaxf(fabsf(v.x), fabsf(v.y)),
                           fmaxf(fabsf(v.z), fabsf(v.w))));
    }
#pragma unroll
    for (int o = 16; o; o >>= 1) m = fmaxf(m, __shfl_xor_sync(0xffffffffu, m, o));
    if ((threadIdx.x & 31) == 0) red[threadIdx.x >> 5] = m;
    __syncthreads();
    if (threadIdx.x < 8) {
        m = red[threadIdx.x];
#pragma unroll
        for (int o = 4; o; o >>= 1) m = fmaxf(m, __shfl_xor_sync(0xffu, m, o));
        if (threadIdx.x == 0) atomicMax(out, __float_as_int(m));
    }
}

// ---------------------------------------------------------------------------
// Quantize kernels: q = round(v * 127 / amax), |v| <= amax -> no clamp needed.
// ---------------------------------------------------------------------------
__device__ __forceinline__ uint32_t pack_s8x4(float4 v, float s) {
    int a = __float2int_rn(v.x * s), b = __float2int_rn(v.y * s);
    int c = __float2int_rn(v.z * s), d = __float2int_rn(v.w * s);
    return (a & 0xFF) | ((b & 0xFF) << 8) | ((c & 0xFF) << 16) | ((d & 0xFF) << 24);
}

__global__ void quant_x_kernel(const float* __restrict__ src) {
    size_t i = (size_t)blockIdx.x * 256 + threadIdx.x;   // float4 index
    float s = 127.f / __int_as_float(g_amax_x);
    float4 v = reinterpret_cast<const float4*>(src)[i];
    reinterpret_cast<uint32_t*>(g_Ax8)[i] = pack_s8x4(v, s);
}

__global__ void quant_e_kernel(const float* __restrict__ src) {
    size_t i = (size_t)blockIdx.x * 256 + threadIdx.x;
    float s = 127.f / __int_as_float(g_amax_e);
    float4 v = reinterpret_cast<const float4*>(src)[i];
    reinterpret_cast<uint32_t*>(g_Be8)[i] = pack_s8x4(v, s);
}

// ---------------------------------------------------------------------------
// Top-8 insert on embedded-score floats (descending)
// ---------------------------------------------------------------------------
__device__ __forceinline__ void top8_ins(float* b, float s) {
    if (s <= b[7]) return;
    int p = 7;
#pragma unroll
    for (int t = 0; t < 7; ++t) {
        if (p > 0 && s > b[p - 1]) { b[p] = b[p - 1]; --p; }
    }
    b[p] = s;
}

// ---------------------------------------------------------------------------
// Main kernel: s8 IMMA, warp tile 64x32, warp-private B pipelines, 4 stages.
// No bar.sync anywhere in the k-loop.
// ---------------------------------------------------------------------------
__global__ void __launch_bounds__(NTHR, 2)
vq_main_kernel() {
    extern __shared__ char smem[];
    uint32_t sb = smem_u32(smem);

    const int tid  = threadIdx.x;
    const int lane = tid & 31;
    const int w    = tid >> 5;     // warp 0..7: owns codes [w*32, w*32+32) per chunk
    const int q    = lane & 3;
    const int m0   = blockIdx.x * MT;

    // Dequant constant: dot_f ~= I * C
    const float C = (__int_as_float(g_amax_x) / 127.f)
                  * (__int_as_float(g_amax_e) / 127.f);

    // ---- Prologue: persistent A int8 (64 x 512 B, cooperative, group G0) ----
#pragma unroll
    for (int j = 0; j < 8; ++j) {             // 2048 16B chunks
        int id = tid + j * 256;
        int row = id >> 5, c = id & 31;       // 32 chunks per 512B row
        const void* src = g_Ax8 + (size_t)(m0 + row) * DIM + c * 16;
        cp_async16(sb + SM_A + a_off(row, c), src);
    }

    // Per-thread B-fill constants. Thread covers rows row0+8j (j=0..3), chunk c0.
    const int row0 = lane >> 2;               // 0..7
    const int c0   = lane & 3;
    uint64_t gB;
    asm("cvta.to.global.u64 %0, %1;" : "=l"(gB) : "l"(g_Be8));
    const uint64_t pbase = gB
        + (uint32_t)((w * 32 + row0) * 512 + c0 * 16);                // bytes
    const uint32_t d0 = (uint32_t)(w * W_SLICE + row0 * 64
                                   + ((c0 ^ ((row0 >> 1) & 3)) * 16));

    // Fill gs=0 (G0 with A), gs=1 (G1), gs=2 (G2).
    // gs: ch = gs>>3, st = gs&7; src off = (ch<<17) + (st<<6).
#pragma unroll
    for (int g = 0; g < 3; ++g) {
        uint32_t fb = sb + SM_B + g * B_STAGE + d0;
        uint64_t src = pbase + (uint32_t)(g << 6);       // ch=0 for g<8
#pragma unroll
        for (int j = 0; j < 4; ++j) cp_async16g(fb + j * 512, src + j * 4096);
        CP_COMMIT();
    }

    asm volatile("cp.async.wait_group 2;" ::: "memory");  // G0: A + slice0
    __syncthreads();                                      // A visible to all

    // per-thread running top-2 (embedded-index floats) for 8 row-slots [mf][h]
    float tb1[4][2], tb2[4][2];
#pragma unroll
    for (int a = 0; a < 4; ++a)
#pragma unroll
        for (int b = 0; b < 2; ++b) { tb1[a][b] = -FLT_MAX; tb2[a][b] = -FLT_MAX; }

#pragma unroll 1
    for (int ch = 0; ch < NCHUNK; ++ch) {
        const int n0 = ch * BN;

        int acc[4][4][4];
#pragma unroll
        for (int a = 0; a < 4; ++a)
#pragma unroll
            for (int b = 0; b < 4; ++b)
#pragma unroll
                for (int c = 0; c < 4; ++c) acc[a][b][c] = 0;

#pragma unroll 1
        for (int st = 0; st < KSTEPS; ++st) {
            const int gs = ch * KSTEPS + st;

            // ---- A fragments for sub 0 (persistent smem; no dependency) ----
            uint32_t afr[4][4];
#pragma unroll
            for (int mf = 0; mf < 4; ++mf) {
                int row = mf * 16 + (lane & 15);
                int cA  = (st * 2) * 2 + (lane >> 4);    // k32 index st*2
                ldmatrix_x4(afr[mf][0], afr[mf][1], afr[mf][2], afr[mf][3],
                            sb + SM_A + a_off(row, cA));
            }

            // Own fill of stage gs%4 complete (fills gs+1, gs+2 in flight).
            asm volatile("cp.async.wait_group 2;" ::: "memory");

            // Refill stage (gs+3)%4 (this warp finished reading it at gs-1).
            if (gs + 3 < NSTEPS) {
                const int g3 = gs + 3;
                uint64_t src = pbase
                    + (uint32_t)(((g3 >> 3) << 17) + ((g3 & 7) << 6));
                uint32_t fb = sb + SM_B + ((g3 & 3) * B_STAGE) + d0;
#pragma unroll
                for (int j = 0; j < 4; ++j)
                    cp_async16g(fb + j * 512, src + j * 4096);
                CP_COMMIT();
            } else {
                CP_COMMIT();           // keep group arithmetic uniform
            }

            const uint32_t bb = sb + SM_B + (gs & 3) * B_STAGE + w * W_SLICE;

#pragma unroll
            for (int sub = 0; sub < 2; ++sub) {        // 2 x k32 per BK=64
                if (sub == 1) {
#pragma unroll
                    for (int mf = 0; mf < 4; ++mf) {
                        int row = mf * 16 + (lane & 15);
                        int cA  = (st * 2 + 1) * 2 + (lane >> 4);
                        ldmatrix_x4(afr[mf][0], afr[mf][1],
                                    afr[mf][2], afr[mf][3],
                                    sb + SM_A + a_off(row, cA));
                    }
                }
                // ---- B fragments: 4 n-frags (8 codes) = 2 ldmatrix.x4 ----
                uint32_t bfr[4][2];
#pragma unroll
                for (int p = 0; p < 2; ++p) {
                    int mi   = lane >> 3;
                    int noff = (mi >> 1) * 8;
                    int kc   = mi & 1;
                    int rloc = p * 16 + noff + (lane & 7);   // 0..31
                    int c    = sub * 2 + kc;                 // 0..3
                    uint32_t addr = bb + rloc * 64
                                    + ((c ^ ((rloc >> 1) & 3)) * 16);
                    ldmatrix_x4(bfr[p*2][0], bfr[p*2][1],
                                bfr[p*2+1][0], bfr[p*2+1][1], addr);
                }
#pragma unroll
                for (int mf = 0; mf < 4; ++mf)
#pragma unroll
                    for (int nf = 0; nf < 4; ++nf)
                        mma_s8(acc[mf][nf][0], acc[mf][nf][1],
                               acc[mf][nf][2], acc[mf][nf][3],
                               afr[mf][0], afr[mf][1], afr[mf][2], afr[mf][3],
                               bfr[nf][0], bfr[nf][1]);
            }
        }

        // ---- epilogue: s = fmaf((float)I, C, -e2/2); branchless top-2 ----
        float e2h[8];
#pragma unroll
        for (int nf = 0; nf < 4; ++nf) {
            float2 p = *reinterpret_cast<const float2*>(
                &g_e2[n0 + w * 32 + nf * 8 + q * 2]);
            e2h[nf * 2] = 0.5f * p.x; e2h[nf * 2 + 1] = 0.5f * p.y;
        }
#pragma unroll
        for (int mf = 0; mf < 4; ++mf)
#pragma unroll
            for (int h = 0; h < 2; ++h)
#pragma unroll
                for (int nf = 0; nf < 4; ++nf) {
                    uint32_t cloc = (uint32_t)(n0 + w * 32 + nf * 8 + q * 2);
                    float f0 = (float)acc[mf][nf][h*2+0];
                    float f1 = (float)acc[mf][nf][h*2+1];
                    float s0 = embed_idx(fmaf(f0, C, -e2h[nf*2+0]), cloc);
                    float s1 = embed_idx(fmaf(f1, C, -e2h[nf*2+1]), cloc + 1);
                    top2f(tb1[mf][h], tb2[mf][h], s0);
                    top2f(tb1[mf][h], tb2[mf][h], s1);
                }
    }

    // ---- final merge: 32 contributors x top-2 per row -> top-8 ----
    asm volatile("cp.async.wait_group 0;" ::: "memory");   // drain tail groups
    __syncthreads();                       // B stages dead; alias merge buffer
    float2* mbuf = reinterpret_cast<float2*>(smem + SM_B); // [64 rows][32]
#pragma unroll
    for (int mf = 0; mf < 4; ++mf)
#pragma unroll
        for (int h = 0; h < 2; ++h) {
            int row = mf * 16 + h * 8 + (lane >> 2);
            mbuf[row * 32 + w * 4 + q] = make_float2(tb1[mf][h], tb2[mf][h]);
        }
    __syncthreads();
    if (tid < MT) {
        float bs[8];
#pragma unroll
        for (int e = 0; e < 8; ++e) bs[e] = -FLT_MAX;
        for (int e = 0; e < 32; ++e) {
            float2 v = mbuf[tid * 32 + e];
            top8_ins(bs, v.x);
            top8_ins(bs, v.y);
        }
#pragma unroll
        for (int e = 0; e < 8; ++e)
            g_top8[m0 + tid][e] = (int)(__float_as_uint(bs[e]) & IDXMASK);
    }
}

// ---------------------------------------------------------------------------
// Refine + gather: exact fp32 re-score of top-8, copy the winner row.
// ---------------------------------------------------------------------------
__global__ void refine_gather_kernel(const float* __restrict__ x,
                                     const float* __restrict__ emb,
                                     float* __restrict__ out) {
    int row  = (blockIdx.x * blockDim.x + threadIdx.x) >> 5;
    int lane = threadIdx.x & 31;
    int cand[8];
#pragma unroll
    for (int c = 0; c < 8; ++c) cand[c] = g_top8[row][c];

    const float4* xr = reinterpret_cast<const float4*>(x + (size_t)row * DIM);
    float d[8] = {0.f, 0.f, 0.f, 0.f, 0.f, 0.f, 0.f, 0.f};
#pragma unroll
    for (int j = 0; j < 4; ++j) {
        float4 xv = xr[lane + j * 32];
#pragma unroll
        for (int c = 0; c < 8; ++c) {
            const float4* er = reinterpret_cast<const float4*>(
                emb + (size_t)cand[c] * DIM);
            float4 e = er[lane + j * 32];
            d[c] += xv.x * e.x + xv.y * e.y + xv.z * e.z + xv.w * e.w;
        }
    }
#pragma unroll
    for (int o = 16; o; o >>= 1)
#pragma unroll
        for (int c = 0; c < 8; ++c)
            d[c] += __shfl_xor_sync(0xffffffffu, d[c], o);

    float bs = d[0] - 0.5f * g_e2[cand[0]];
    int   bi = cand[0];
#pragma unroll
    for (int c = 1; c < 8; ++c) {
        float s = d[c] - 0.5f * g_e2[cand[c]];
        if (s > bs || (s == bs && cand[c] < bi)) { bs = s; bi = cand[c]; }
    }

    const float4* src = reinterpret_cast<const float4*>(emb + (size_t)bi * DIM);
    float4*       dst = reinterpret_cast<float4*>(out + (size_t)row * DIM);
#pragma unroll
    for (int j = 0; j < 4; ++j) dst[lane + j * 32] = src[lane + j * 32];
}

// ---------------------------------------------------------------------------
extern "C" void kernel_launch(void* const* d_in, const int* in_sizes, int n_in,
                              void* d_out, int out_size) {
    const float* x   = (const float*)d_in[0];
    const float* emb = (const float*)d_in[1];
    float*       out = (float*)d_out;

    cudaFuncSetAttribute(vq_main_kernel,
                         cudaFuncAttributeMaxDynamicSharedMemorySize, SMEM_TOTAL);

    int* d_amax_x; cudaGetSymbolAddress((void**)&d_amax_x, g_amax_x);
    int* d_amax_e; cudaGetSymbolAddress((void**)&d_amax_e, g_amax_e);

    e2_kernel<<<K_CODES / 8, 256>>>(emb);
    amax_kernel<<<512, 256>>>(x,   (size_t)M_TOTAL * DIM / 4, d_amax_x);
    amax_kernel<<<512, 256>>>(emb, (size_t)K_CODES * DIM / 4, d_amax_e);
    quant_x_kernel<<<(M_TOTAL * DIM / 4) / 256, 256>>>(x);
    quant_e_kernel<<<(K_CODES * DIM / 4) / 256, 256>>>(emb);
    vq_main_kernel<<<M_TOTAL / MT, NTHR, SMEM_TOTAL>>>();
    refine_gather_kernel<<<M_TOTAL / 8, 256>>>(x, emb, out);
}

// round 13
// speedup vs baseline: 2.8976x; 2.8976x over previous
#include <cuda_runtime.h>
#include <cuda_bf16.h>
#include <cstdint>
#include <cfloat>

// ---------------------------------------------------------------------------
// Problem constants
// ---------------------------------------------------------------------------
#define M_TOTAL 16384
#define K_CODES 8192
#define DIM     512
#define MT      64              // rows per CTA (2 CTAs/SM)
#define BN      256             // codes per chunk; warp tile 64x32
#define NCHUNK  (K_CODES / BN)  // 32
#define BK      32              // bf16 K per pipeline step (64 B/row)
#define KSTEPS  (DIM / BK)      // 16
#define NSTEPS  (NCHUNK * KSTEPS) // 512
#define NTHR    256
#define IDXMASK 0x1FFFu         // 13 bits: code index embedded in mantissa

// ---------------------------------------------------------------------------
// Scratch (static device arrays: allocation-free rule)
// ---------------------------------------------------------------------------
__device__ __nv_bfloat16 g_Ab[(size_t)M_TOTAL * DIM];   // bf16(x)   16 MB
__device__ __nv_bfloat16 g_Bb[(size_t)K_CODES * DIM];   // bf16(emb)  8 MB
__device__ float g_e2[K_CODES];
__device__ int   g_top8[M_TOTAL][8];

// ---------------------------------------------------------------------------
// Baseline-PTX helpers (no "a"-suffix arch features)
// ---------------------------------------------------------------------------
__device__ __forceinline__ uint32_t smem_u32(const void* p) {
    uint32_t a;
    asm("{ .reg .u64 t; cvta.to.shared.u64 t, %1; cvt.u32.u64 %0, t; }"
        : "=r"(a) : "l"(p));
    return a;
}

__device__ __forceinline__ void cp_async16(uint32_t dst, const void* src) {
    uint64_t g;
    asm("cvta.to.global.u64 %0, %1;" : "=l"(g) : "l"(src));
    asm volatile("cp.async.cg.shared.global [%0], [%1], 16;"
                 :: "r"(dst), "l"(g) : "memory");
}

// Pre-converted global address variant (no per-call cvta).
__device__ __forceinline__ void cp_async16g(uint32_t dst, uint64_t gsrc) {
    asm volatile("cp.async.cg.shared.global [%0], [%1], 16;"
                 :: "r"(dst), "l"(gsrc) : "memory");
}
#define CP_COMMIT() asm volatile("cp.async.commit_group;" ::: "memory")

__device__ __forceinline__ void ldmatrix_x4(uint32_t& r0, uint32_t& r1,
                                            uint32_t& r2, uint32_t& r3,
                                            uint32_t addr) {
    asm volatile("ldmatrix.sync.aligned.m8n8.x4.shared.b16 {%0,%1,%2,%3}, [%4];"
                 : "=r"(r0), "=r"(r1), "=r"(r2), "=r"(r3) : "r"(addr));
}

__device__ __forceinline__ void mma_bf16(float& d0, float& d1, float& d2, float& d3,
                                         uint32_t a0, uint32_t a1, uint32_t a2, uint32_t a3,
                                         uint32_t b0, uint32_t b1) {
    asm volatile(
        "mma.sync.aligned.m16n8k16.row.col.f32.bf16.bf16.f32 "
        "{%0,%1,%2,%3}, {%4,%5,%6,%7}, {%8,%9}, {%0,%1,%2,%3};"
        : "+f"(d0), "+f"(d1), "+f"(d2), "+f"(d3)
        : "r"(a0), "r"(a1), "r"(a2), "r"(a3), "r"(b0), "r"(b1));
}

// Embed code index in low 13 mantissa bits (single LOP3).
__device__ __forceinline__ float embed_idx(float s, uint32_t idx) {
    uint32_t r;
    asm("lop3.b32 %0, %1, %2, %3, 0xEA;"     // (a & b) | c
        : "=r"(r) : "r"(__float_as_uint(s)), "r"(~IDXMASK), "r"(idx));
    return __uint_as_float(r);
}

// Branchless top-2 (values carry their index).
__device__ __forceinline__ void top2f(float& b1, float& b2, float s) {
    float hi = fmaxf(b1, s);
    float lo = fminf(b1, s);
    b1 = hi;
    b2 = fmaxf(b2, lo);
}

// ---------------------------------------------------------------------------
// SMEM layout: A persistent 64 KB + B 3 stages x 16 KB -> 112 KB, 2 CTAs/SM.
// Each B stage = 8 warp-private slices of 2 KB (32 rows x 64 B).
// ---------------------------------------------------------------------------
#define SM_A       0                          // 64 rows x 1024 B
#define SM_B       65536
#define B_STAGE    16384
#define W_SLICE    2048
#define SMEM_TOTAL (SM_B + 3 * B_STAGE)       // 114688

// ---------------------------------------------------------------------------
// Fused kernel: g_Bb = bf16(emb), g_e2[k] = ||emb_k||^2 (one emb read pass)
// One warp per row.
// ---------------------------------------------------------------------------
__global__ void cvt_e2_kernel(const float* __restrict__ emb) {
    int row  = blockIdx.x * 8 + (threadIdx.x >> 5);
    int lane = threadIdx.x & 31;
    const float4* p = reinterpret_cast<const float4*>(emb + (size_t)row * DIM);
    __nv_bfloat162* o = reinterpret_cast<__nv_bfloat162*>(g_Bb) + (size_t)row * 256;
    float s = 0.f;
#pragma unroll
    for (int i = 0; i < 4; ++i) {
        int idx = lane + i * 32;
        float4 v = p[idx];
        s += v.x * v.x + v.y * v.y + v.z * v.z + v.w * v.w;
        o[idx * 2 + 0] = __floats2bfloat162_rn(v.x, v.y);
        o[idx * 2 + 1] = __floats2bfloat162_rn(v.z, v.w);
    }
#pragma unroll
    for (int off = 16; off; off >>= 1) s += __shfl_xor_sync(0xffffffffu, s, off);
    if (lane == 0) g_e2[row] = s;
}

// ---------------------------------------------------------------------------
// bf16 convert kernel for x
// ---------------------------------------------------------------------------
__global__ void cvt_x_kernel(const float* __restrict__ src) {
    size_t i = (size_t)blockIdx.x * 256 + threadIdx.x;   // float4 units
    float4 v = reinterpret_cast<const float4*>(src)[i];
    reinterpret_cast<__nv_bfloat162*>(g_Ab)[i * 2 + 0] = __floats2bfloat162_rn(v.x, v.y);
    reinterpret_cast<__nv_bfloat162*>(g_Ab)[i * 2 + 1] = __floats2bfloat162_rn(v.z, v.w);
}

// ---------------------------------------------------------------------------
// Top-8 insert on embedded-score floats (descending)
// ---------------------------------------------------------------------------
__device__ __forceinline__ void top8_ins(float* b, float s) {
    if (s <= b[7]) return;
    int p = 7;
#pragma unroll
    for (int t = 0; t < 7; ++t) {
        if (p > 0 && s > b[p - 1]) { b[p] = b[p - 1]; --p; }
    }
    b[p] = s;
}

// ---------------------------------------------------------------------------
// Main kernel: bf16 HMMA, warp tile 64x32, fully warp-private B pipelines.
// No bar.sync anywhere in the k-loop. (Proven R11 structure.)
// ---------------------------------------------------------------------------
__global__ void __launch_bounds__(NTHR, 2)
vq_main_kernel() {
    extern __shared__ char smem[];
    uint32_t sb = smem_u32(smem);

    const int tid  = threadIdx.x;
    const int lane = tid & 31;
    const int w    = tid >> 5;     // warp 0..7: owns codes [w*32, w*32+32) per chunk
    const int q    = lane & 3;
    const int m0   = blockIdx.x * MT;

    // ---- Prologue: persistent A (cooperative; part of group G0) ----
#pragma unroll
    for (int j = 0; j < 16; ++j) {            // 4096 16B chunks
        int id = tid + j * 256;
        int row = id >> 6, c = id & 63;       // 64 chunks per 1024B row
        const void* src = g_Ab + (size_t)(m0 + row) * DIM + c * 8;
        uint32_t dst = sb + SM_A + row * 1024 + (c >> 3) * 128
                       + (((c & 7) ^ (row & 7)) * 16);
        cp_async16(dst, src);
    }

    // Per-thread B-fill constants. Thread covers rows row0+8j (j=0..3), chunk c0.
    // swz is j-invariant: ((row0+8j)>>1)&3 == (row0>>1)&3.
    const int row0 = lane >> 2;               // 0..7
    const int c0   = lane & 3;
    uint64_t gB;
    asm("cvta.to.global.u64 %0, %1;" : "=l"(gB) : "l"(g_Bb));
    const uint64_t pbase = gB
        + (uint32_t)(((w * 32 + row0) * 512 + c0 * 8) * 2);           // bytes
    const uint32_t d0 = (uint32_t)(w * W_SLICE + row0 * 64
                                   + ((c0 ^ ((row0 >> 1) & 3)) * 16));

    // Fill gs=0 (group G0, with A) and gs=1 (G1). gs: ch=gs>>4, st=gs&15.
    {
        uint32_t fb = sb + SM_B + 0 * B_STAGE + d0;
#pragma unroll
        for (int j = 0; j < 4; ++j) cp_async16g(fb + j * 512, pbase + j * 8192);
        CP_COMMIT();
    }
    {
        uint32_t fb = sb + SM_B + 1 * B_STAGE + d0;
#pragma unroll
        for (int j = 0; j < 4; ++j) cp_async16g(fb + j * 512, pbase + 64 + j * 8192);
        CP_COMMIT();
    }

    asm volatile("cp.async.wait_group 1;" ::: "memory");   // G0: A + slice0
    __syncthreads();                                       // A visible to all

    // per-thread running top-2 (embedded-index floats) for 8 row-slots [mf][h]
    float tb1[4][2], tb2[4][2];
#pragma unroll
    for (int a = 0; a < 4; ++a)
#pragma unroll
        for (int b = 0; b < 2; ++b) { tb1[a][b] = -FLT_MAX; tb2[a][b] = -FLT_MAX; }

    int sr = 0;                                // gs % 3
#pragma unroll 1
    for (int ch = 0; ch < NCHUNK; ++ch) {
        const int n0 = ch * BN;

        float acc[4][4][4];
#pragma unroll
        for (int a = 0; a < 4; ++a)
#pragma unroll
            for (int b = 0; b < 4; ++b)
#pragma unroll
                for (int c = 0; c < 4; ++c) acc[a][b][c] = 0.f;

#pragma unroll 1
        for (int st = 0; st < KSTEPS; ++st) {
            const int gs = ch * KSTEPS + st;

            // ---- A fragments for sub 0 (persistent smem; no dependency) ----
            uint32_t afr[4][4];
#pragma unroll
            for (int mf = 0; mf < 4; ++mf) {
                int row = mf * 16 + (lane & 15);
                int cA  = (st * 2) * 2 + (lane >> 4);   // k16 = st*2
                uint32_t addr = sb + SM_A + row * 1024 + (cA >> 3) * 128
                                + (((cA & 7) ^ (row & 7)) * 16);
                ldmatrix_x4(afr[mf][0], afr[mf][1], afr[mf][2], afr[mf][3], addr);
            }

            // Refill stage (gs+2)%3 BEFORE the wait (legal: this warp finished
            // reading that stage at step gs-1; issuing earlier hides fill
            // latency one commit sooner). wait_group 1 below then completes
            // everything except this newest group.
            const int sf = (sr >= 1) ? (sr - 1) : 2;
            if (gs + 2 < NSTEPS) {
                const int g2 = gs + 2;
                uint64_t src = pbase
                    + (uint32_t)(((g2 >> 4) << 18) + ((g2 & 15) << 6));
                uint32_t fb = sb + SM_B + sf * B_STAGE + d0;
#pragma unroll
                for (int j = 0; j < 4; ++j)
                    cp_async16g(fb + j * 512, src + j * 8192);
                CP_COMMIT();
            } else {
                CP_COMMIT();           // keep group arithmetic uniform
            }

            // Own fill of stage gs%3 complete (newest group stays in flight).
            asm volatile("cp.async.wait_group 1;" ::: "memory");

            const uint32_t bb = sb + SM_B + sr * B_STAGE + w * W_SLICE;

#pragma unroll
            for (int sub = 0; sub < 2; ++sub) {        // 2 x k16 per BK=32
                if (sub == 1) {
                    // A fragments for sub 1 (reuse afr registers)
#pragma unroll
                    for (int mf = 0; mf < 4; ++mf) {
                        int row = mf * 16 + (lane & 15);
                        int cA  = (st * 2 + 1) * 2 + (lane >> 4);
                        uint32_t addr = sb + SM_A + row * 1024 + (cA >> 3) * 128
                                        + (((cA & 7) ^ (row & 7)) * 16);
                        ldmatrix_x4(afr[mf][0], afr[mf][1],
                                    afr[mf][2], afr[mf][3], addr);
                    }
                }
                // ---- B fragments: 4 n-frags (8 codes each) = 2 ldmatrix.x4 ----
                uint32_t bfr[4][2];
#pragma unroll
                for (int p = 0; p < 2; ++p) {
                    int mi   = lane >> 3;
                    int noff = (mi >> 1) * 8;
                    int kc   = mi & 1;
                    int rloc = p * 16 + noff + (lane & 7);   // 0..31
                    int c    = sub * 2 + kc;
                    uint32_t addr = bb + rloc * 64
                                    + ((c ^ ((rloc >> 1) & 3)) * 16);
                    ldmatrix_x4(bfr[p*2][0], bfr[p*2][1],
                                bfr[p*2+1][0], bfr[p*2+1][1], addr);
                }
#pragma unroll
                for (int mf = 0; mf < 4; ++mf)
#pragma unroll
                    for (int nf = 0; nf < 4; ++nf)
                        mma_bf16(acc[mf][nf][0], acc[mf][nf][1],
                                 acc[mf][nf][2], acc[mf][nf][3],
                                 afr[mf][0], afr[mf][1], afr[mf][2], afr[mf][3],
                                 bfr[nf][0], bfr[nf][1]);
            }
            sr = (sr == 2) ? 0 : sr + 1;
        }

        // ---- epilogue: branchless embedded-index top-2 (no barriers) ----
        float e2h[8];
#pragma unroll
        for (int nf = 0; nf < 4; ++nf) {
            float2 p = *reinterpret_cast<const float2*>(
                &g_e2[n0 + w * 32 + nf * 8 + q * 2]);
            e2h[nf * 2] = 0.5f * p.x; e2h[nf * 2 + 1] = 0.5f * p.y;
        }
#pragma unroll
        for (int mf = 0; mf < 4; ++mf)
#pragma unroll
            for (int h = 0; h < 2; ++h)
#pragma unroll
                for (int nf = 0; nf < 4; ++nf) {
                    uint32_t cloc = (uint32_t)(n0 + w * 32 + nf * 8 + q * 2);
                    float s0 = embed_idx(acc[mf][nf][h*2+0] - e2h[nf*2+0], cloc);
                    float s1 = embed_idx(acc[mf][nf][h*2+1] - e2h[nf*2+1], cloc + 1);
                    top2f(tb1[mf][h], tb2[mf][h], s0);
                    top2f(tb1[mf][h], tb2[mf][h], s1);
                }
    }

    // ---- final merge: 32 contributors x top-2 per row -> top-8 ----
    asm volatile("cp.async.wait_group 0;" ::: "memory");   // drain tail groups
    __syncthreads();                       // B stages dead; alias merge buffer
    float2* mbuf = reinterpret_cast<float2*>(smem + SM_B); // [64 rows][32]
#pragma unroll
    for (int mf = 0; mf < 4; ++mf)
#pragma unroll
        for (int h = 0; h < 2; ++h) {
            int row = mf * 16 + h * 8 + (lane >> 2);
            mbuf[row * 32 + w * 4 + q] = make_float2(tb1[mf][h], tb2[mf][h]);
        }
    __syncthreads();
    if (tid < MT) {
        float bs[8];
#pragma unroll
        for (int e = 0; e < 8; ++e) bs[e] = -FLT_MAX;
        for (int e = 0; e < 32; ++e) {
            float2 v = mbuf[tid * 32 + e];
            top8_ins(bs, v.x);
            top8_ins(bs, v.y);
        }
#pragma unroll
        for (int e = 0; e < 8; ++e)
            g_top8[m0 + tid][e] = (int)(__float_as_uint(bs[e]) & IDXMASK);
    }
}

// ---------------------------------------------------------------------------
// Refine + gather: exact fp32 re-score of top-8, copy the winner row.
// ---------------------------------------------------------------------------
__global__ void refine_gather_kernel(const float* __restrict__ x,
                                     const float* __restrict__ emb,
                                     float* __restrict__ out) {
    int row  = (blockIdx.x * blockDim.x + threadIdx.x) >> 5;
    int lane = threadIdx.x & 31;
    int cand[8];
#pragma unroll
    for (int c = 0; c < 8; ++c) cand[c] = g_top8[row][c];

    const float4* xr = reinterpret_cast<const float4*>(x + (size_t)row * DIM);
    float d[8] = {0.f, 0.f, 0.f, 0.f, 0.f, 0.f, 0.f, 0.f};
#pragma unroll
    for (int j = 0; j < 4; ++j) {
        float4 xv = xr[lane + j * 32];
#pragma unroll
        for (int c = 0; c < 8; ++c) {
            const float4* er = reinterpret_cast<const float4*>(
                emb + (size_t)cand[c] * DIM);
            float4 e = er[lane + j * 32];
            d[c] += xv.x * e.x + xv.y * e.y + xv.z * e.z + xv.w * e.w;
        }
    }
#pragma unroll
    for (int o = 16; o; o >>= 1)
#pragma unroll
        for (int c = 0; c < 8; ++c)
            d[c] += __shfl_xor_sync(0xffffffffu, d[c], o);

    float bs = d[0] - 0.5f * g_e2[cand[0]];
    int   bi = cand[0];
#pragma unroll
    for (int c = 1; c < 8; ++c) {
        float s = d[c] - 0.5f * g_e2[cand[c]];
        if (s > bs || (s == bs && cand[c] < bi)) { bs = s; bi = cand[c]; }
    }

    const float4* src = reinterpret_cast<const float4*>(emb + (size_t)bi * DIM);
    float4*       dst = reinterpret_cast<float4*>(out + (size_t)row * DIM);
#pragma unroll
    for (int j = 0; j < 4; ++j) dst[lane + j * 32] = src[lane + j * 32];
}

// ---------------------------------------------------------------------------
extern "C" void kernel_launch(void* const* d_in, const int* in_sizes, int n_in,
                              void* d_out, int out_size) {
    const float* x   = (const float*)d_in[0];
    const float* emb = (const float*)d_in[1];
    float*       out = (float*)d_out;

    cudaFuncSetAttribute(vq_main_kernel,
                         cudaFuncAttributeMaxDynamicSharedMemorySize, SMEM_TOTAL);

    cvt_e2_kernel<<<K_CODES / 8, 256>>>(emb);
    cvt_x_kernel<<<(M_TOTAL * DIM / 4) / 256, 256>>>(x);
    vq_main_kernel<<<M_TOTAL / MT, NTHR, SMEM_TOTAL>>>();
    refine_gather_kernel<<<M_TOTAL / 8, 256>>>(x, emb, out);
}